// round 14
// baseline (speedup 1.0000x reference)
#include <cuda_runtime.h>
#include <cuda_bf16.h>
#include <math.h>

// Problem dims
#define NB   256      // batch (sentences)
#define LT   128      // tokens per sentence
#define DI   300      // embedding dim
#define EE   512      // LSTM hidden
#define G4   2048     // 4*E
#define FF   4096     // 2*E*HOP
#define HOPS 4
#define NLAB 7
#define NLTOT (NB*LT) // 32768

// ---------------- device scratch ----------------
__device__ float g_emb[(size_t)NLTOT * DI];        // 39 MB
__device__ float g_xg [(size_t)NLTOT * 4096];      // 537 MB : [n*128+l][dir*2048 + gate*512 + e]
__device__ float g_enc[(size_t)NLTOT * 1024];      // 134 MB : [n*128+l][dir*512 + e]
__device__ float g_h2[2 * 2 * NB * EE];            // [parity][dir][n][e]
__device__ float g_Mh[HOPS * 1024];
__device__ float g_s0[HOPS];
__device__ float g_attw[(size_t)NLTOT * HOPS];
__device__ float g_sent[(size_t)NB * FF];          // [n][e*4+h]
__device__ float g_sxg [(size_t)NB * 4096];        // [n][dir*2048 + gate*512 + e]
__device__ float g_sh[2 * 2 * EE];                 // [parity][dir][e]
__device__ float g_sout[(size_t)NB * 1024];        // [n][dir*512+e]
__device__ float g_bias_tok[4096];
__device__ float g_bias_sent[4096];
__device__ unsigned g_bar_cnt[8];
__device__ unsigned g_bar_flag[8];

__device__ __forceinline__ float sigf(float x) { return 1.f / (1.f + __expf(-x)); }

__device__ __forceinline__ unsigned f2tf32(float x)
{
    unsigned u;
    asm("cvt.rna.tf32.f32 %0, %1;" : "=r"(u) : "f"(x));
    return u;
}

__device__ __forceinline__ float4 cvt4(float4 v)
{
    v.x = __uint_as_float(f2tf32(v.x));
    v.y = __uint_as_float(f2tf32(v.y));
    v.z = __uint_as_float(f2tf32(v.z));
    v.w = __uint_as_float(f2tf32(v.w));
    return v;
}

__device__ __forceinline__ void mma8(float* c, const unsigned* a, const unsigned* b)
{
    asm volatile(
        "mma.sync.aligned.m16n8k8.row.col.f32.tf32.tf32.f32 "
        "{%0,%1,%2,%3},{%4,%5,%6,%7},{%8,%9},{%0,%1,%2,%3};"
        : "+f"(c[0]), "+f"(c[1]), "+f"(c[2]), "+f"(c[3])
        : "r"(a[0]), "r"(a[1]), "r"(a[2]), "r"(a[3]), "r"(b[0]), "r"(b[1]));
}

// grid barrier — round-6 proven form: arrival AND poll are strong atomics.
__device__ __forceinline__ void grid_bar_strong(int slot, unsigned arrivals, unsigned step)
{
    if (threadIdx.x == 0) {
        __threadfence();
        unsigned v = atomicAdd(&g_bar_cnt[slot], 1u);
        if (v == arrivals - 1u) {
            g_bar_cnt[slot] = 0u;
            __threadfence();
            atomicExch(&g_bar_flag[slot], step);
        } else {
            while (atomicAdd(&g_bar_flag[slot], 0u) < step) { }
            __threadfence();
        }
    }
    __syncthreads();
}

#define CP_ASYNC16(dst32, src) \
    asm volatile("cp.async.ca.shared.global [%0], [%1], 16;" :: "r"(dst32), "l"(src))
#define CP_COMMIT() asm volatile("cp.async.commit_group;")
#define CP_WAIT0()  asm volatile("cp.async.wait_group 0;")

// ---------------- tf32 SGEMM 128x128, 2-stage smem ping-pong: C = A @ B^T (+bias[n]) ----
#define BM 128
#define BN 128
#define BK 16
#define AST 20   // (20*qr+qc) mod 32 all-distinct => conflict-free frag loads
#define BST 20

__device__ __forceinline__ float4 ldA(const float* ap, int kbase, int K)
{
    float4 v;
    if (kbase + 4 <= K) v = *(const float4*)ap;
    else {
        v.x = (kbase + 0 < K) ? ap[0] : 0.f;
        v.y = (kbase + 1 < K) ? ap[1] : 0.f;
        v.z = (kbase + 2 < K) ? ap[2] : 0.f;
        v.w = (kbase + 3 < K) ? ap[3] : 0.f;
    }
    return v;
}

__device__ __forceinline__ void gemm_tf32_body(
    const float* __restrict__ A, int lda,
    const float* __restrict__ B, int ldb,
    const float* __restrict__ bias,
    float* __restrict__ C, int ldc,
    int K, int m0, int n0,
    float* As, float* Bs)   // each holds 2 stages
{
    int tid = threadIdx.x;                 // 256 threads
    int warp = tid >> 5, lane = tid & 31;
    int wm = warp >> 2;                    // 0..1 -> m offset wm*64
    int wn = warp & 3;                     // 0..3 -> n offset wn*32
    int qr = lane >> 2;
    int qc = lane & 3;

    int lr = tid >> 2;                     // 0..63 (loader row)
    int lc = (tid & 3) << 2;               // 0,4,8,12 (loader k)

    float acc[4][4][4];
#pragma unroll
    for (int mf = 0; mf < 4; mf++)
#pragma unroll
        for (int nf = 0; nf < 4; nf++)
#pragma unroll
            for (int r = 0; r < 4; r++) acc[mf][nf][r] = 0.f;

    // preload k0 = 0
    float4 ra0 = ldA(A + (size_t)(m0 + lr) * lda + lc, lc, K);
    float4 ra1 = ldA(A + (size_t)(m0 + lr + 64) * lda + lc, lc, K);
    float4 rb0 = ldA(B + (size_t)(n0 + lr) * ldb + lc, lc, K);
    float4 rb1 = ldA(B + (size_t)(n0 + lr + 64) * ldb + lc, lc, K);

    int it = 0;
    for (int k0 = 0; k0 < K; k0 += BK, it ^= 1) {
        float* Asp = As + it * (BM * AST);
        float* Bsp = Bs + it * (BN * BST);
        *(float4*)&Asp[lr * AST + lc] = cvt4(ra0);
        *(float4*)&Asp[(lr + 64) * AST + lc] = cvt4(ra1);
        *(float4*)&Bsp[lr * BST + lc] = cvt4(rb0);
        *(float4*)&Bsp[(lr + 64) * BST + lc] = cvt4(rb1);
        __syncthreads();

        int kn = k0 + BK;
        if (kn < K) {
            ra0 = ldA(A + (size_t)(m0 + lr) * lda + kn + lc, kn + lc, K);
            ra1 = ldA(A + (size_t)(m0 + lr + 64) * lda + kn + lc, kn + lc, K);
            rb0 = ldA(B + (size_t)(n0 + lr) * ldb + kn + lc, kn + lc, K);
            rb1 = ldA(B + (size_t)(n0 + lr + 64) * ldb + kn + lc, kn + lc, K);
        }

#pragma unroll
        for (int kk = 0; kk < BK; kk += 8) {
            unsigned af[4][4], bf[4][2];
#pragma unroll
            for (int mf = 0; mf < 4; mf++) {
                int mb = (wm << 6) + (mf << 4) + qr;
                af[mf][0] = __float_as_uint(Asp[mb * AST + kk + qc]);
                af[mf][1] = __float_as_uint(Asp[(mb + 8) * AST + kk + qc]);
                af[mf][2] = __float_as_uint(Asp[mb * AST + kk + qc + 4]);
                af[mf][3] = __float_as_uint(Asp[(mb + 8) * AST + kk + qc + 4]);
            }
#pragma unroll
            for (int nf = 0; nf < 4; nf++) {
                int nb = (wn << 5) + (nf << 3) + qr;
                bf[nf][0] = __float_as_uint(Bsp[nb * BST + kk + qc]);
                bf[nf][1] = __float_as_uint(Bsp[nb * BST + kk + qc + 4]);
            }
#pragma unroll
            for (int mf = 0; mf < 4; mf++)
#pragma unroll
                for (int nf = 0; nf < 4; nf++)
                    mma8(acc[mf][nf], af[mf], bf[nf]);
        }
    }

#pragma unroll
    for (int mf = 0; mf < 4; mf++) {
#pragma unroll
        for (int nf = 0; nf < 4; nf++) {
            int n = n0 + (wn << 5) + (nf << 3) + (qc << 1);
#pragma unroll
            for (int rh = 0; rh < 2; rh++) {
                int m = m0 + (wm << 6) + (mf << 4) + qr + (rh << 3);
                float2 v;
                v.x = acc[mf][nf][rh * 2 + 0];
                v.y = acc[mf][nf][rh * 2 + 1];
                if (bias) { v.x += bias[n]; v.y += bias[n + 1]; }
                *(float2*)&C[(size_t)m * ldc + n] = v;
            }
        }
    }
}

__global__ void gemm2_kernel(const float* __restrict__ A, int lda,
                             const float* __restrict__ B0, const float* __restrict__ B1,
                             int ldb, const float* __restrict__ bias4096,
                             float* __restrict__ C, int ldc, int K)
{
    __shared__ float As[2 * BM * AST];
    __shared__ float Bs[2 * BN * BST];
    int dir = blockIdx.z;
    const float* B = dir ? B1 : B0;
    const float* bias = bias4096 ? (bias4096 + dir * 2048) : nullptr;
    gemm_tf32_body(A, lda, B, ldb, bias,
                   C + dir * 2048, ldc, K, blockIdx.y * BM, blockIdx.x * BN, As, Bs);
}

// ---------------- persistent token BiLSTM scan — 512 threads / 16 warps ----------------
// 128 blocks: dir(2) x batch-half(2) x e-slice(32, 16 e each). One wave, 1 block/SM.
// Same tile (128 batch x 64 gate-rows), same k-order, same smem protocol as round 10;
// only the intra-block partitioning changed: warp tile 32x16 (was 32x32).
#define TOK_WST 516          // Ws row stride: (4*qr+qc) distinct mod 32 -> conflict-free
#define TOK_HST 36           // Hb row stride (36 mod 32 = 4) -> conflict-free frags
#define TOK_OST 68           // Os row stride (68 mod 32 = 4)
#define XST     68           // Xs row stride
#define TOK_HB0 (64 * TOK_WST)
#define TOK_XS  (64 * TOK_WST + 2 * 128 * TOK_HST)
#define TOK_SMEM ((64 * TOK_WST + 2 * 128 * TOK_HST + 128 * XST) * 4)

__global__ void __launch_bounds__(512, 1) tok_scan_kernel(
    const float* __restrict__ whh_f, const float* __restrict__ whh_b)
{
    extern __shared__ float sm[];
    float* Ws = sm;                 // 64 x 516 tf32 weights (132KB, resident)
    float* Os = sm + TOK_HB0;       // 128 x 68 gemm output (aliases the two Hb buffers)
    float* Xs = sm + TOK_XS;        // 128 x 68 xg gate tile

    int tid = threadIdx.x;
    int warp = tid >> 5, lane = tid & 31;
    int wm = warp & 3;               // m block: wm*32
    int wn = warp >> 2;              // n block: wn*16 (0..3)
    int qr = lane >> 2, qc = lane & 3;

    int dir = blockIdx.x >> 6;
    int rem = blockIdx.x & 63;
    int bh = rem >> 5;           // batch half
    int es = rem & 31;           // e-slice (16 e each)
    int e_base = es << 4;
    int nb0 = bh << 7;
    int bslot = dir * 2 + bh;    // barrier slot, 32 arrivals each

    const float* whh = dir ? whh_b : whh_f;

    // load Whh rows {gate*512 + e_base + el}, gate-major (16 e per gate), once
    for (int idx = tid * 4; idx < 64 * 512; idx += 2048) {
        int r = idx >> 9, k = idx & 511;
        int gate = r >> 4, el = r & 15;
        float4 w = cvt4(*(const float4*)&whh[(size_t)((gate << 9) + e_base + el) * 512 + k]);
        *(float4*)&Ws[r * TOK_WST + k] = w;
    }

    int gp_e = tid & 15;         // gate-phase cell coords
    int gp_n = tid >> 4;         // 0..31
    float creg[4];
#pragma unroll
    for (int j = 0; j < 4; j++) creg[j] = 0.f;

    // h chunk loader: 512 threads cover 128 rows x 32 floats (2 float4 each)
    int clr = tid >> 2;          // 0..127 (row)
    int clc = (tid & 3) << 3;    // 0,8,16,24

    unsigned xs_addr = (unsigned)__cvta_generic_to_shared(Xs);

    __syncthreads();

    for (int s = 0; s < LT; s++) {
        int p = s & 1;
        int l = dir ? (LT - 1 - s) : s;

        // issue async xg gate-tile loads (128 rows x 4 gates x 16 floats)
        {
            const float* xbase = g_xg + (size_t)(nb0 * LT + l) * 4096 + (dir << 11) + e_base;
#pragma unroll
            for (int j = 0; j < 4; j++) {
                int i = tid + (j << 9);          // 0..2047
                int row = i >> 4;
                int q = i & 15;
                int gate = q >> 2, v4 = (q & 3) << 2;
                const float* src = xbase + (size_t)row * (LT * 4096) + (gate << 9) + v4;
                CP_ASYNC16(xs_addr + (unsigned)((row * XST + (gate << 4) + v4) << 2), src);
            }
            CP_COMMIT();
        }

        const float* hsrc = g_h2 + (size_t)((p * 2 + dir) * NB + nb0) * EE;

        float acc[2][2][4];
#pragma unroll
        for (int mf = 0; mf < 2; mf++)
#pragma unroll
            for (int nf = 0; nf < 2; nf++)
#pragma unroll
                for (int r = 0; r < 4; r++) acc[mf][nf][r] = 0.f;

        // preload chunk 0 (128 rows x 32 k): 2 float4 per thread
        float4 pre0 = *(const float4*)(hsrc + (size_t)clr * EE + clc);
        float4 pre1 = *(const float4*)(hsrc + (size_t)clr * EE + clc + 4);

        // 2-stage ping-pong: STS(ck) -> sync -> prefetch(ck+1) + mma(ck)
        for (int ck = 0; ck < 16; ck++) {
            float* Hc = sm + TOK_HB0 + (ck & 1) * (128 * TOK_HST);
            int k0 = ck << 5;
            *(float4*)&Hc[clr * TOK_HST + clc] = cvt4(pre0);
            *(float4*)&Hc[clr * TOK_HST + clc + 4] = cvt4(pre1);
            __syncthreads();

            if (ck < 15) {
                pre0 = *(const float4*)(hsrc + (size_t)clr * EE + k0 + 32 + clc);
                pre1 = *(const float4*)(hsrc + (size_t)clr * EE + k0 + 32 + clc + 4);
            }

#pragma unroll
            for (int kk = 0; kk < 32; kk += 8) {
                unsigned af[2][4], bf[2][2];
#pragma unroll
                for (int mf = 0; mf < 2; mf++) {
                    int mb = (wm << 5) + (mf << 4) + qr;
                    af[mf][0] = __float_as_uint(Hc[mb * TOK_HST + kk + qc]);
                    af[mf][1] = __float_as_uint(Hc[(mb + 8) * TOK_HST + kk + qc]);
                    af[mf][2] = __float_as_uint(Hc[mb * TOK_HST + kk + qc + 4]);
                    af[mf][3] = __float_as_uint(Hc[(mb + 8) * TOK_HST + kk + qc + 4]);
                }
#pragma unroll
                for (int nf = 0; nf < 2; nf++) {
                    int nb = (wn << 4) + (nf << 3) + qr;
                    bf[nf][0] = __float_as_uint(Ws[nb * TOK_WST + k0 + kk + qc]);
                    bf[nf][1] = __float_as_uint(Ws[nb * TOK_WST + k0 + kk + qc + 4]);
                }
#pragma unroll
                for (int mf = 0; mf < 2; mf++)
#pragma unroll
                    for (int nf = 0; nf < 2; nf++)
                        mma8(acc[mf][nf], af[mf], bf[nf]);
            }
        }
        __syncthreads();   // all mma done before Os (aliases Hb buffers) is written

        // dump accumulators to Os
#pragma unroll
        for (int mf = 0; mf < 2; mf++)
#pragma unroll
            for (int nf = 0; nf < 2; nf++) {
                int cc = (wn << 4) + (nf << 3) + (qc << 1);
#pragma unroll
                for (int rh = 0; rh < 2; rh++) {
                    int rr = (wm << 5) + (mf << 4) + qr + (rh << 3);
                    Os[rr * TOK_OST + cc] = acc[mf][nf][rh * 2 + 0];
                    Os[rr * TOK_OST + cc + 1] = acc[mf][nf][rh * 2 + 1];
                }
            }
        CP_WAIT0();
        __syncthreads();

        // gate phase: 4 cells per thread, c in registers, xg from Xs
        float* hdst = g_h2 + (size_t)(((p ^ 1) * 2 + dir) * NB + nb0) * EE;
#pragma unroll
        for (int j = 0; j < 4; j++) {
            int nn = gp_n + (j << 5);
            int ng = nb0 + nn;
            float gi = Os[nn * TOK_OST + gp_e]      + Xs[nn * XST + gp_e];
            float gf = Os[nn * TOK_OST + 16 + gp_e] + Xs[nn * XST + 16 + gp_e];
            float gg = Os[nn * TOK_OST + 32 + gp_e] + Xs[nn * XST + 32 + gp_e];
            float go = Os[nn * TOK_OST + 48 + gp_e] + Xs[nn * XST + 48 + gp_e];
            float c = creg[j];
            c = sigf(gf) * c + sigf(gi) * tanhf(gg);
            float h = sigf(go) * tanhf(c);
            creg[j] = c;
            hdst[(size_t)nn * EE + e_base + gp_e] = h;
            g_enc[((size_t)ng * LT + l) * 1024 + (dir << 9) + e_base + gp_e] = h;
        }
        __syncthreads();

        // per-(dir,bh) grid barrier: 32 arrivals, strong-atomic poll
        grid_bar_strong(bslot, 32u, (unsigned)(s + 1));
    }
}

// ---------------- misc kernels ----------------
// init + bias precompute + attention fold
__global__ void initbias_kernel(const float* b0, const float* b1, const float* b2, const float* b3,
                                const float* s0, const float* s1, const float* s2, const float* s3,
                                const float* __restrict__ W, const float* __restrict__ b,
                                const float* __restrict__ ctx)
{
    int i = blockIdx.x * 256 + threadIdx.x;
    if (i < 2 * 2 * NB * EE) g_h2[i] = 0.f;
    if (i < 2 * 2 * EE) g_sh[i] = 0.f;
    if (i < 8) { g_bar_cnt[i] = 0u; g_bar_flag[i] = 0u; }
    if (i < 2048) {
        g_bias_tok[i] = b0[i] + b1[i];
        g_bias_sent[i] = s0[i] + s1[i];
    } else if (i < 4096) {
        int j = i - 2048;
        g_bias_tok[i] = b2[j] + b3[j];
        g_bias_sent[i] = s2[j] + s3[j];
    }
    if (i < HOPS * 1024) {
        int h = i >> 10, e = i & 1023;
        float s = 0.f;
        for (int a = 0; a < 256; a++) s += ctx[h * 256 + a] * W[a * 1024 + e];
        g_Mh[i] = s;
    }
    if (i < HOPS) {
        float s = 0.f;
        for (int a = 0; a < 256; a++) s += ctx[i * 256 + a] * b[a];
        g_s0[i] = s;
    }
}

__global__ void embed_kernel(const int* __restrict__ tokens,
                             const float* __restrict__ emb)
{
    size_t idx = (size_t)blockIdx.x * 256 + threadIdx.x;
    if (idx >= (size_t)NLTOT * DI) return;
    int nl = (int)(idx / DI);
    int d = (int)(idx - (size_t)nl * DI);
    g_emb[idx] = emb[(size_t)tokens[nl] * DI + d];
}

__global__ void scores_kernel(const int* __restrict__ lengths)
{
    __shared__ float Msh[4096];
    __shared__ float s0s[4];
    int tid = threadIdx.x;
    for (int i = tid; i < 4096; i += 256) Msh[i] = g_Mh[i];
    if (tid < 4) s0s[tid] = g_s0[tid];
    __syncthreads();
    int gid = blockIdx.x * 8 + (tid >> 5);
    int lane = tid & 31;
    int n = gid >> 7, l = gid & 127;
    const float* row = g_enc + (size_t)gid * 1024;
    float a0 = 0, a1 = 0, a2 = 0, a3 = 0;
    for (int e = lane; e < 1024; e += 32) {
        float v = row[e];
        a0 += v * Msh[e];        a1 += v * Msh[1024 + e];
        a2 += v * Msh[2048 + e]; a3 += v * Msh[3072 + e];
    }
#pragma unroll
    for (int o = 16; o > 0; o >>= 1) {
        a0 += __shfl_xor_sync(0xffffffffu, a0, o);
        a1 += __shfl_xor_sync(0xffffffffu, a1, o);
        a2 += __shfl_xor_sync(0xffffffffu, a2, o);
        a3 += __shfl_xor_sync(0xffffffffu, a3, o);
    }
    if (lane == 0) {
        a0 += s0s[0]; a1 += s0s[1]; a2 += s0s[2]; a3 += s0s[3];
        float mx = fmaxf(fmaxf(a0, a1), fmaxf(a2, a3));
        float e0 = __expf(a0 - mx), e1 = __expf(a1 - mx);
        float e2 = __expf(a2 - mx), e3 = __expf(a3 - mx);
        float inv = 1.f / (e0 + e1 + e2 + e3);
        float msk = (l < lengths[n]) ? 1.f : 0.f;
        float4 w = make_float4(e0 * inv * msk, e1 * inv * msk, e2 * inv * msk, e3 * inv * msk);
        *(float4*)&g_attw[(size_t)gid * 4] = w;
    }
}

__global__ void sent_accum_kernel()
{
    int n = blockIdx.x, tid = threadIdx.x;
    float acc[4][4];
#pragma unroll
    for (int j = 0; j < 4; j++)
#pragma unroll
        for (int h = 0; h < 4; h++) acc[j][h] = 0.f;
    const float* encn = g_enc + (size_t)n * LT * 1024;
    const float* wv = g_attw + (size_t)n * LT * 4;
    for (int l = 0; l < LT; l++) {
        float4 w = *(const float4*)&wv[l * 4];
        const float* row = encn + (size_t)l * 1024;
#pragma unroll
        for (int j = 0; j < 4; j++) {
            float v = row[tid + j * 256];
            acc[j][0] += v * w.x; acc[j][1] += v * w.y;
            acc[j][2] += v * w.z; acc[j][3] += v * w.w;
        }
    }
#pragma unroll
    for (int j = 0; j < 4; j++) {
        int e = tid + j * 256;
#pragma unroll
        for (int h = 0; h < 4; h++)
            g_sent[(size_t)n * FF + e * 4 + h] = acc[j][h];
    }
}

// ---------------- persistent sentence BiLSTM scan (barrier slots 4/5) ----------------
#define SENT_NB_PER_DIR 32
#define SENT_SMEM ((16 * 4 * 512 + 512) * 4)

__global__ void sent_scan_kernel(const float* __restrict__ whh_f,
                                 const float* __restrict__ whh_b)
{
    extern __shared__ float sm[];
    float* ws = sm;                 // 16 e * 4 gates * 512 k
    float* hs = sm + 16 * 4 * 512;  // 512
    int dir = blockIdx.x >> 5;
    int bslot = blockIdx.x & 31;
    int e_base = bslot * 16;
    const float* whh = dir ? whh_b : whh_f;
    int tid = threadIdx.x;

    for (int idx = tid * 4; idx < 32768; idx += 256 * 4) {
        int gate = idx >> 13;
        int rem = idx & 8191;
        int el = rem >> 9;
        int k = rem & 511;
        *(float4*)&ws[idx] =
            *(const float4*)&whh[(size_t)((gate << 9) + e_base + el) * 512 + k];
    }
    int warp = tid >> 5, lane = tid & 31;
    int group = lane >> 3, lane8 = lane & 7;
    float creg[2] = {0.f, 0.f};
    __syncthreads();

    for (int s = 0; s < 256; s++) {
        int rd = s & 1;
        for (int i = tid; i < 512; i += 256)
            hs[i] = __ldcg(&g_sh[(rd * 2 + dir) * 512 + i]);
        __syncthreads();
        int nt = dir ? (255 - s) : s;
        const float* xrow = g_sxg + (size_t)nt * 4096 + (dir << 11);
#pragma unroll
        for (int i = 0; i < 2; i++) {
            int el = (warp << 1) + i;
            int e = e_base + el;
            const float4* w4 = (const float4*)&ws[((group << 4) + el) << 9];
            const float4* h4 = (const float4*)hs;
            float acc = 0.f;
#pragma unroll
            for (int m = 0; m < 16; m++) {
                float4 a = w4[lane8 + (m << 3)];
                float4 b = h4[lane8 + (m << 3)];
                acc += a.x * b.x + a.y * b.y + a.z * b.z + a.w * b.w;
            }
            acc += __shfl_xor_sync(0xffffffffu, acc, 1);
            acc += __shfl_xor_sync(0xffffffffu, acc, 2);
            acc += __shfl_xor_sync(0xffffffffu, acc, 4);
            float g = acc + xrow[(group << 9) + e];
            float gi = __shfl_sync(0xffffffffu, g, 0);
            float gf = __shfl_sync(0xffffffffu, g, 8);
            float gg = __shfl_sync(0xffffffffu, g, 16);
            float go = __shfl_sync(0xffffffffu, g, 24);
            if (lane == 0) {
                float c = creg[i];
                c = sigf(gf) * c + sigf(gi) * tanhf(gg);
                float h = sigf(go) * tanhf(c);
                creg[i] = c;
                int wr = rd ^ 1;
                g_sh[(wr * 2 + dir) * 512 + e] = h;
                g_sout[(size_t)nt * 1024 + (dir << 9) + e] = h;
            }
        }
        __syncthreads();
        grid_bar_strong(4 + dir, (unsigned)SENT_NB_PER_DIR, (unsigned)(s + 1));
    }
}

__global__ void final_kernel(const float* __restrict__ lw,
                             const float* __restrict__ lb,
                             float* __restrict__ out)
{
    int n = blockIdx.x, lane = threadIdx.x;
    const float* s = g_sout + (size_t)n * 1024;
    for (int c = 0; c < NLAB; c++) {
        float a = 0.f;
        for (int e = lane; e < 1024; e += 32) a += s[e] * lw[c * 1024 + e];
#pragma unroll
        for (int o = 16; o > 0; o >>= 1) a += __shfl_xor_sync(0xffffffffu, a, o);
        if (lane == 0) out[n * NLAB + c] = a + lb[c];
    }
}

// ---------------- launch ----------------
extern "C" void kernel_launch(void* const* d_in, const int* in_sizes, int n_in,
                              void* d_out, int out_size)
{
    const int*   tokens     = (const int*)d_in[0];
    const int*   lengths    = (const int*)d_in[1];
    const float* embedding  = (const float*)d_in[2];
    const float* tok_Wih_f  = (const float*)d_in[3];
    const float* tok_Whh_f  = (const float*)d_in[4];
    const float* tok_bih_f  = (const float*)d_in[5];
    const float* tok_bhh_f  = (const float*)d_in[6];
    const float* tok_Wih_b  = (const float*)d_in[7];
    const float* tok_Whh_b  = (const float*)d_in[8];
    const float* tok_bih_b  = (const float*)d_in[9];
    const float* tok_bhh_b  = (const float*)d_in[10];
    const float* attn_W     = (const float*)d_in[11];
    const float* attn_b     = (const float*)d_in[12];
    const float* attn_ctx   = (const float*)d_in[13];
    const float* sent_Wih_f = (const float*)d_in[14];
    const float* sent_Whh_f = (const float*)d_in[15];
    const float* sent_bih_f = (const float*)d_in[16];
    const float* sent_bhh_f = (const float*)d_in[17];
    const float* sent_Wih_b = (const float*)d_in[18];
    const float* sent_Whh_b = (const float*)d_in[19];
    const float* sent_bih_b = (const float*)d_in[20];
    const float* sent_bhh_b = (const float*)d_in[21];
    const float* lin_W      = (const float*)d_in[22];
    const float* lin_b      = (const float*)d_in[23];
    float* out = (float*)d_out;

    float *p_emb, *p_xg, *p_sent, *p_sxg, *p_btok, *p_bsent;
    cudaGetSymbolAddress((void**)&p_emb, g_emb);
    cudaGetSymbolAddress((void**)&p_xg, g_xg);
    cudaGetSymbolAddress((void**)&p_sent, g_sent);
    cudaGetSymbolAddress((void**)&p_sxg, g_sxg);
    cudaGetSymbolAddress((void**)&p_btok, g_bias_tok);
    cudaGetSymbolAddress((void**)&p_bsent, g_bias_sent);

    cudaFuncSetAttribute(sent_scan_kernel,
                         cudaFuncAttributeMaxDynamicSharedMemorySize, SENT_SMEM);
    cudaFuncSetAttribute(tok_scan_kernel,
                         cudaFuncAttributeMaxDynamicSharedMemorySize, TOK_SMEM);

    // launch 1: init state + bias precompute + attention fold (merged)
    initbias_kernel<<<2048, 256>>>(tok_bih_f, tok_bhh_f, tok_bih_b, tok_bhh_b,
                                   sent_bih_f, sent_bhh_f, sent_bih_b, sent_bhh_b,
                                   attn_W, attn_b, attn_ctx);
    // launch 2: embedding gather
    embed_kernel<<<(int)(((size_t)NLTOT * DI + 255) / 256), 256>>>(tokens, embedding);
    // launch 3: xg = emb @ [Wih_f;Wih_b]^T + biases (128x128 tiles, 2-stage)
    gemm2_kernel<<<dim3(16, 256, 2), 256>>>(p_emb, DI, tok_Wih_f, tok_Wih_b, DI,
                                            p_btok, p_xg, 4096, DI);
    // launch 4: persistent token BiLSTM scan, 512 threads (profiler slot)
    tok_scan_kernel<<<128, 512, TOK_SMEM>>>(tok_Whh_f, tok_Whh_b);

    // attention scores/softmax (full-grid streaming) + sentence feature
    scores_kernel<<<4096, 256>>>(lengths);
    sent_accum_kernel<<<256, 256>>>();

    // sentence input projection (M=256, N=2048/dir, K=4096)
    gemm2_kernel<<<dim3(16, 2, 2), 256>>>(p_sent, FF, sent_Wih_f, sent_Wih_b, FF,
                                          p_bsent, p_sxg, 4096, FF);

    // persistent sentence BiLSTM
    sent_scan_kernel<<<64, 256, SENT_SMEM>>>(sent_Whh_f, sent_Whh_b);

    final_kernel<<<256, 32>>>(lin_W, lin_b, out);
}

// round 15
// speedup vs baseline: 1.0806x; 1.0806x over previous
#include <cuda_runtime.h>
#include <cuda_bf16.h>
#include <math.h>

// Problem dims
#define NB   256      // batch (sentences)
#define LT   128      // tokens per sentence
#define DI   300      // embedding dim
#define EE   512      // LSTM hidden
#define G4   2048     // 4*E
#define FF   4096     // 2*E*HOP
#define HOPS 4
#define NLAB 7
#define NLTOT (NB*LT) // 32768

// ---------------- device scratch ----------------
__device__ float g_emb[(size_t)NLTOT * DI];        // 39 MB
__device__ float g_xg [(size_t)NLTOT * 4096];      // 537 MB : [n*128+l][dir*2048 + gate*512 + e]
__device__ float g_enc[(size_t)NLTOT * 1024];      // 134 MB : [n*128+l][dir*512 + e]
__device__ float g_h2[2 * 2 * NB * EE];            // [parity][dir][n][e]
__device__ float g_Mh[HOPS * 1024];
__device__ float g_s0[HOPS];
__device__ float g_attw[(size_t)NLTOT * HOPS];
__device__ float g_sent[(size_t)NB * FF];          // [n][e*4+h]
__device__ float g_sxg [(size_t)NB * 4096];        // [n][dir*2048 + gate*512 + e]
__device__ float g_sh[2 * 2 * EE];                 // [parity][dir][e]
__device__ float g_sout[(size_t)NB * 1024];        // [n][dir*512+e]
__device__ float g_bias_tok[4096];
__device__ float g_bias_sent[4096];
__device__ unsigned g_bar_cnt[8];
__device__ unsigned g_bar_flag[8];

__device__ __forceinline__ float sigf(float x) { return 1.f / (1.f + __expf(-x)); }

__device__ __forceinline__ unsigned f2tf32(float x)
{
    unsigned u;
    asm("cvt.rna.tf32.f32 %0, %1;" : "=r"(u) : "f"(x));
    return u;
}

__device__ __forceinline__ float4 cvt4(float4 v)
{
    v.x = __uint_as_float(f2tf32(v.x));
    v.y = __uint_as_float(f2tf32(v.y));
    v.z = __uint_as_float(f2tf32(v.z));
    v.w = __uint_as_float(f2tf32(v.w));
    return v;
}

__device__ __forceinline__ void mma8(float* c, const unsigned* a, const unsigned* b)
{
    asm volatile(
        "mma.sync.aligned.m16n8k8.row.col.f32.tf32.tf32.f32 "
        "{%0,%1,%2,%3},{%4,%5,%6,%7},{%8,%9},{%0,%1,%2,%3};"
        : "+f"(c[0]), "+f"(c[1]), "+f"(c[2]), "+f"(c[3])
        : "r"(a[0]), "r"(a[1]), "r"(a[2]), "r"(a[3]), "r"(b[0]), "r"(b[1]));
}

// grid barrier — round-6 proven form: arrival AND poll are strong atomics.
__device__ __forceinline__ void grid_bar_strong(int slot, unsigned arrivals, unsigned step)
{
    if (threadIdx.x == 0) {
        __threadfence();
        unsigned v = atomicAdd(&g_bar_cnt[slot], 1u);
        if (v == arrivals - 1u) {
            g_bar_cnt[slot] = 0u;
            __threadfence();
            atomicExch(&g_bar_flag[slot], step);
        } else {
            while (atomicAdd(&g_bar_flag[slot], 0u) < step) { }
            __threadfence();
        }
    }
    __syncthreads();
}

#define CP_ASYNC16(dst32, src) \
    asm volatile("cp.async.ca.shared.global [%0], [%1], 16;" :: "r"(dst32), "l"(src))
#define CP_COMMIT() asm volatile("cp.async.commit_group;")
#define CP_WAIT0()  asm volatile("cp.async.wait_group 0;")

// ---------------- tf32 SGEMM 128x128, 2-stage smem ping-pong: C = A @ B^T (+bias[n]) ----
#define BM 128
#define BN 128
#define BK 16
#define AST 20   // (20*qr+qc) mod 32 all-distinct => conflict-free frag loads
#define BST 20

__device__ __forceinline__ float4 ldA(const float* ap, int kbase, int K)
{
    float4 v;
    if (kbase + 4 <= K) v = *(const float4*)ap;
    else {
        v.x = (kbase + 0 < K) ? ap[0] : 0.f;
        v.y = (kbase + 1 < K) ? ap[1] : 0.f;
        v.z = (kbase + 2 < K) ? ap[2] : 0.f;
        v.w = (kbase + 3 < K) ? ap[3] : 0.f;
    }
    return v;
}

__device__ __forceinline__ void gemm_tf32_body(
    const float* __restrict__ A, int lda,
    const float* __restrict__ B, int ldb,
    const float* __restrict__ bias,
    float* __restrict__ C, int ldc,
    int K, int m0, int n0,
    float* As, float* Bs)   // each holds 2 stages
{
    int tid = threadIdx.x;                 // 256 threads
    int warp = tid >> 5, lane = tid & 31;
    int wm = warp >> 2;                    // 0..1 -> m offset wm*64
    int wn = warp & 3;                     // 0..3 -> n offset wn*32
    int qr = lane >> 2;
    int qc = lane & 3;

    int lr = tid >> 2;                     // 0..63 (loader row)
    int lc = (tid & 3) << 2;               // 0,4,8,12 (loader k)

    float acc[4][4][4];
#pragma unroll
    for (int mf = 0; mf < 4; mf++)
#pragma unroll
        for (int nf = 0; nf < 4; nf++)
#pragma unroll
            for (int r = 0; r < 4; r++) acc[mf][nf][r] = 0.f;

    // preload k0 = 0
    float4 ra0 = ldA(A + (size_t)(m0 + lr) * lda + lc, lc, K);
    float4 ra1 = ldA(A + (size_t)(m0 + lr + 64) * lda + lc, lc, K);
    float4 rb0 = ldA(B + (size_t)(n0 + lr) * ldb + lc, lc, K);
    float4 rb1 = ldA(B + (size_t)(n0 + lr + 64) * ldb + lc, lc, K);

    int it = 0;
    for (int k0 = 0; k0 < K; k0 += BK, it ^= 1) {
        float* Asp = As + it * (BM * AST);
        float* Bsp = Bs + it * (BN * BST);
        *(float4*)&Asp[lr * AST + lc] = cvt4(ra0);
        *(float4*)&Asp[(lr + 64) * AST + lc] = cvt4(ra1);
        *(float4*)&Bsp[lr * BST + lc] = cvt4(rb0);
        *(float4*)&Bsp[(lr + 64) * BST + lc] = cvt4(rb1);
        __syncthreads();

        int kn = k0 + BK;
        if (kn < K) {
            ra0 = ldA(A + (size_t)(m0 + lr) * lda + kn + lc, kn + lc, K);
            ra1 = ldA(A + (size_t)(m0 + lr + 64) * lda + kn + lc, kn + lc, K);
            rb0 = ldA(B + (size_t)(n0 + lr) * ldb + kn + lc, kn + lc, K);
            rb1 = ldA(B + (size_t)(n0 + lr + 64) * ldb + kn + lc, kn + lc, K);
        }

#pragma unroll
        for (int kk = 0; kk < BK; kk += 8) {
            unsigned af[4][4], bf[4][2];
#pragma unroll
            for (int mf = 0; mf < 4; mf++) {
                int mb = (wm << 6) + (mf << 4) + qr;
                af[mf][0] = __float_as_uint(Asp[mb * AST + kk + qc]);
                af[mf][1] = __float_as_uint(Asp[(mb + 8) * AST + kk + qc]);
                af[mf][2] = __float_as_uint(Asp[mb * AST + kk + qc + 4]);
                af[mf][3] = __float_as_uint(Asp[(mb + 8) * AST + kk + qc + 4]);
            }
#pragma unroll
            for (int nf = 0; nf < 4; nf++) {
                int nb = (wn << 5) + (nf << 3) + qr;
                bf[nf][0] = __float_as_uint(Bsp[nb * BST + kk + qc]);
                bf[nf][1] = __float_as_uint(Bsp[nb * BST + kk + qc + 4]);
            }
#pragma unroll
            for (int mf = 0; mf < 4; mf++)
#pragma unroll
                for (int nf = 0; nf < 4; nf++)
                    mma8(acc[mf][nf], af[mf], bf[nf]);
        }
    }

#pragma unroll
    for (int mf = 0; mf < 4; mf++) {
#pragma unroll
        for (int nf = 0; nf < 4; nf++) {
            int n = n0 + (wn << 5) + (nf << 3) + (qc << 1);
#pragma unroll
            for (int rh = 0; rh < 2; rh++) {
                int m = m0 + (wm << 6) + (mf << 4) + qr + (rh << 3);
                float2 v;
                v.x = acc[mf][nf][rh * 2 + 0];
                v.y = acc[mf][nf][rh * 2 + 1];
                if (bias) { v.x += bias[n]; v.y += bias[n + 1]; }
                *(float2*)&C[(size_t)m * ldc + n] = v;
            }
        }
    }
}

__global__ void gemm2_kernel(const float* __restrict__ A, int lda,
                             const float* __restrict__ B0, const float* __restrict__ B1,
                             int ldb, const float* __restrict__ bias4096,
                             float* __restrict__ C, int ldc, int K)
{
    __shared__ float As[2 * BM * AST];
    __shared__ float Bs[2 * BN * BST];
    int dir = blockIdx.z;
    const float* B = dir ? B1 : B0;
    const float* bias = bias4096 ? (bias4096 + dir * 2048) : nullptr;
    gemm_tf32_body(A, lda, B, ldb, bias,
                   C + dir * 2048, ldc, K, blockIdx.y * BM, blockIdx.x * BN, As, Bs);
}

// ---------------- persistent token BiLSTM scan (256 threads, round-10 proven shape) ----
// 128 blocks: dir(2) x batch-half(2) x e-slice(32, 16 e each). One wave, 1 block/SM.
// NEW: Ws stored in pair-permuted k-layout (k=qc and k=qc+4 adjacent) with row
// stride 520 (== 8 mod 32) so B-fragment loads are conflict-free LDS.64.
#define TOK_WST 520          // Ws row stride (8 mod 32): LDS.64 banks 8qr+2qc distinct/phase
#define TOK_HST 36           // Hb row stride (36 mod 32 = 4) -> conflict-free scalar frags
#define TOK_OST 68           // Os row stride (68 mod 32 = 4)
#define XST     68           // Xs row stride
#define TOK_HB0 (64 * TOK_WST)
#define TOK_XS  (64 * TOK_WST + 2 * 128 * TOK_HST)
#define TOK_SMEM ((64 * TOK_WST + 2 * 128 * TOK_HST + 128 * XST) * 4)

__global__ void __launch_bounds__(256, 1) tok_scan_kernel(
    const float* __restrict__ whh_f, const float* __restrict__ whh_b)
{
    extern __shared__ float sm[];
    float* Ws = sm;                 // 64 x 520 tf32 weights, pair-permuted k (133KB)
    float* Os = sm + TOK_HB0;       // 128 x 68 gemm output (aliases the two Hb buffers)
    float* Xs = sm + TOK_XS;        // 128 x 68 xg gate tile

    int tid = threadIdx.x;
    int warp = tid >> 5, lane = tid & 31;
    int wm = warp & 3, wn = warp >> 2;
    int qr = lane >> 2, qc = lane & 3;

    int dir = blockIdx.x >> 6;
    int rem = blockIdx.x & 63;
    int bh = rem >> 5;           // batch half
    int es = rem & 31;           // e-slice (16 e each)
    int e_base = es << 4;
    int nb0 = bh << 7;
    int bslot = dir * 2 + bh;    // barrier slot, 32 arrivals each

    const float* whh = dir ? whh_b : whh_f;

    // load Whh rows {gate*512 + e_base + el}, gate-major, once — PAIR-PERMUTED k:
    // within each 8-group, original k goes to position 2*(k&3) + ((k>>2)&1),
    // so (k=qc, k=qc+4) land adjacent at (2qc, 2qc+1).
    for (int idx = tid * 4; idx < 64 * 512; idx += 1024) {
        int r = idx >> 9, k = idx & 511;          // k multiple of 4
        int gate = r >> 4, el = r & 15;
        float4 w = cvt4(*(const float4*)&whh[(size_t)((gate << 9) + e_base + el) * 512 + k]);
        int base = r * TOK_WST + (k & ~7);
        int off = (k & 4) ? 1 : 0;                // k%8==4 -> odd positions
        Ws[base + off + 0] = w.x;
        Ws[base + off + 2] = w.y;
        Ws[base + off + 4] = w.z;
        Ws[base + off + 6] = w.w;
    }

    int gp_e = tid & 15;         // gate-phase cell coords
    int gp_n = tid >> 4;         // 0..15
    float creg[8];
#pragma unroll
    for (int j = 0; j < 8; j++) creg[j] = 0.f;

    // h chunk loader: warp covers 4 rows x 32 floats; 4 passes of 32 rows
    int clr = tid >> 3;          // 0..31
    int clc = (tid & 7) << 2;    // 0,4,...,28

    unsigned xs_addr = (unsigned)__cvta_generic_to_shared(Xs);

    __syncthreads();

    for (int s = 0; s < LT; s++) {
        int p = s & 1;
        int l = dir ? (LT - 1 - s) : s;

        // issue async xg gate-tile loads (128 rows x 4 gates x 16 floats)
        {
            const float* xbase = g_xg + (size_t)(nb0 * LT + l) * 4096 + (dir << 11) + e_base;
#pragma unroll
            for (int j = 0; j < 8; j++) {
                int i = tid + (j << 8);          // 0..2047
                int row = i >> 4;
                int q = i & 15;
                int gate = q >> 2, v4 = (q & 3) << 2;
                const float* src = xbase + (size_t)row * (LT * 4096) + (gate << 9) + v4;
                CP_ASYNC16(xs_addr + (unsigned)((row * XST + (gate << 4) + v4) << 2), src);
            }
            CP_COMMIT();
        }

        const float* hsrc = g_h2 + (size_t)((p * 2 + dir) * NB + nb0) * EE;

        float acc[2][4][4];
#pragma unroll
        for (int mf = 0; mf < 2; mf++)
#pragma unroll
            for (int nf = 0; nf < 4; nf++)
#pragma unroll
                for (int r = 0; r < 4; r++) acc[mf][nf][r] = 0.f;

        // preload chunk 0 (128 rows x 32 k)
        float4 pre[4];
#pragma unroll
        for (int pp = 0; pp < 4; pp++)
            pre[pp] = *(const float4*)(hsrc + (size_t)(clr + (pp << 5)) * EE + clc);

        // 2-stage ping-pong: STS(ck) -> sync -> prefetch(ck+1) + mma(ck)
        for (int ck = 0; ck < 16; ck++) {
            float* Hc = sm + TOK_HB0 + (ck & 1) * (128 * TOK_HST);
            int k0 = ck << 5;
#pragma unroll
            for (int pp = 0; pp < 4; pp++)
                *(float4*)&Hc[(clr + (pp << 5)) * TOK_HST + clc] = cvt4(pre[pp]);
            __syncthreads();

            if (ck < 15) {
#pragma unroll
                for (int pp = 0; pp < 4; pp++)
                    pre[pp] = *(const float4*)(hsrc + (size_t)(clr + (pp << 5)) * EE + k0 + 32 + clc);
            }

#pragma unroll
            for (int kk = 0; kk < 32; kk += 8) {
                unsigned af[2][4], bf[4][2];
#pragma unroll
                for (int mf = 0; mf < 2; mf++) {
                    int mb = (wm << 5) + (mf << 4) + qr;
                    af[mf][0] = __float_as_uint(Hc[mb * TOK_HST + kk + qc]);
                    af[mf][1] = __float_as_uint(Hc[(mb + 8) * TOK_HST + kk + qc]);
                    af[mf][2] = __float_as_uint(Hc[mb * TOK_HST + kk + qc + 4]);
                    af[mf][3] = __float_as_uint(Hc[(mb + 8) * TOK_HST + kk + qc + 4]);
                }
#pragma unroll
                for (int nf = 0; nf < 4; nf++) {
                    int nb = (wn << 5) + (nf << 3) + qr;
                    float2 b2 = *(const float2*)&Ws[nb * TOK_WST + k0 + kk + (qc << 1)];
                    bf[nf][0] = __float_as_uint(b2.x);
                    bf[nf][1] = __float_as_uint(b2.y);
                }
#pragma unroll
                for (int mf = 0; mf < 2; mf++)
#pragma unroll
                    for (int nf = 0; nf < 4; nf++)
                        mma8(acc[mf][nf], af[mf], bf[nf]);
            }
        }
        __syncthreads();   // all mma done before Os (aliases Hb buffers) is written

        // dump accumulators to Os
#pragma unroll
        for (int mf = 0; mf < 2; mf++)
#pragma unroll
            for (int nf = 0; nf < 4; nf++) {
                int cc = (wn << 5) + (nf << 3) + (qc << 1);
#pragma unroll
                for (int rh = 0; rh < 2; rh++) {
                    int rr = (wm << 5) + (mf << 4) + qr + (rh << 3);
                    Os[rr * TOK_OST + cc] = acc[mf][nf][rh * 2 + 0];
                    Os[rr * TOK_OST + cc + 1] = acc[mf][nf][rh * 2 + 1];
                }
            }
        CP_WAIT0();
        __syncthreads();

        // gate phase: 8 cells per thread, c in registers, xg from Xs
        float* hdst = g_h2 + (size_t)(((p ^ 1) * 2 + dir) * NB + nb0) * EE;
#pragma unroll
        for (int j = 0; j < 8; j++) {
            int nn = gp_n + (j << 4);
            int ng = nb0 + nn;
            float gi = Os[nn * TOK_OST + gp_e]      + Xs[nn * XST + gp_e];
            float gf = Os[nn * TOK_OST + 16 + gp_e] + Xs[nn * XST + 16 + gp_e];
            float gg = Os[nn * TOK_OST + 32 + gp_e] + Xs[nn * XST + 32 + gp_e];
            float go = Os[nn * TOK_OST + 48 + gp_e] + Xs[nn * XST + 48 + gp_e];
            float c = creg[j];
            c = sigf(gf) * c + sigf(gi) * tanhf(gg);
            float h = sigf(go) * tanhf(c);
            creg[j] = c;
            hdst[(size_t)nn * EE + e_base + gp_e] = h;
            g_enc[((size_t)ng * LT + l) * 1024 + (dir << 9) + e_base + gp_e] = h;
        }
        __syncthreads();

        // per-(dir,bh) grid barrier: 32 arrivals, strong-atomic poll
        grid_bar_strong(bslot, 32u, (unsigned)(s + 1));
    }
}

// ---------------- misc kernels ----------------
// init + bias precompute + attention fold
__global__ void initbias_kernel(const float* b0, const float* b1, const float* b2, const float* b3,
                                const float* s0, const float* s1, const float* s2, const float* s3,
                                const float* __restrict__ W, const float* __restrict__ b,
                                const float* __restrict__ ctx)
{
    int i = blockIdx.x * 256 + threadIdx.x;
    if (i < 2 * 2 * NB * EE) g_h2[i] = 0.f;
    if (i < 2 * 2 * EE) g_sh[i] = 0.f;
    if (i < 8) { g_bar_cnt[i] = 0u; g_bar_flag[i] = 0u; }
    if (i < 2048) {
        g_bias_tok[i] = b0[i] + b1[i];
        g_bias_sent[i] = s0[i] + s1[i];
    } else if (i < 4096) {
        int j = i - 2048;
        g_bias_tok[i] = b2[j] + b3[j];
        g_bias_sent[i] = s2[j] + s3[j];
    }
    if (i < HOPS * 1024) {
        int h = i >> 10, e = i & 1023;
        float s = 0.f;
        for (int a = 0; a < 256; a++) s += ctx[h * 256 + a] * W[a * 1024 + e];
        g_Mh[i] = s;
    }
    if (i < HOPS) {
        float s = 0.f;
        for (int a = 0; a < 256; a++) s += ctx[i * 256 + a] * b[a];
        g_s0[i] = s;
    }
}

__global__ void embed_kernel(const int* __restrict__ tokens,
                             const float* __restrict__ emb)
{
    size_t idx = (size_t)blockIdx.x * 256 + threadIdx.x;
    if (idx >= (size_t)NLTOT * DI) return;
    int nl = (int)(idx / DI);
    int d = (int)(idx - (size_t)nl * DI);
    g_emb[idx] = emb[(size_t)tokens[nl] * DI + d];
}

__global__ void scores_kernel(const int* __restrict__ lengths)
{
    __shared__ float Msh[4096];
    __shared__ float s0s[4];
    int tid = threadIdx.x;
    for (int i = tid; i < 4096; i += 256) Msh[i] = g_Mh[i];
    if (tid < 4) s0s[tid] = g_s0[tid];
    __syncthreads();
    int gid = blockIdx.x * 8 + (tid >> 5);
    int lane = tid & 31;
    int n = gid >> 7, l = gid & 127;
    const float* row = g_enc + (size_t)gid * 1024;
    float a0 = 0, a1 = 0, a2 = 0, a3 = 0;
    for (int e = lane; e < 1024; e += 32) {
        float v = row[e];
        a0 += v * Msh[e];        a1 += v * Msh[1024 + e];
        a2 += v * Msh[2048 + e]; a3 += v * Msh[3072 + e];
    }
#pragma unroll
    for (int o = 16; o > 0; o >>= 1) {
        a0 += __shfl_xor_sync(0xffffffffu, a0, o);
        a1 += __shfl_xor_sync(0xffffffffu, a1, o);
        a2 += __shfl_xor_sync(0xffffffffu, a2, o);
        a3 += __shfl_xor_sync(0xffffffffu, a3, o);
    }
    if (lane == 0) {
        a0 += s0s[0]; a1 += s0s[1]; a2 += s0s[2]; a3 += s0s[3];
        float mx = fmaxf(fmaxf(a0, a1), fmaxf(a2, a3));
        float e0 = __expf(a0 - mx), e1 = __expf(a1 - mx);
        float e2 = __expf(a2 - mx), e3 = __expf(a3 - mx);
        float inv = 1.f / (e0 + e1 + e2 + e3);
        float msk = (l < lengths[n]) ? 1.f : 0.f;
        float4 w = make_float4(e0 * inv * msk, e1 * inv * msk, e2 * inv * msk, e3 * inv * msk);
        *(float4*)&g_attw[(size_t)gid * 4] = w;
    }
}

__global__ void sent_accum_kernel()
{
    int n = blockIdx.x, tid = threadIdx.x;
    float acc[4][4];
#pragma unroll
    for (int j = 0; j < 4; j++)
#pragma unroll
        for (int h = 0; h < 4; h++) acc[j][h] = 0.f;
    const float* encn = g_enc + (size_t)n * LT * 1024;
    const float* wv = g_attw + (size_t)n * LT * 4;
    for (int l = 0; l < LT; l++) {
        float4 w = *(const float4*)&wv[l * 4];
        const float* row = encn + (size_t)l * 1024;
#pragma unroll
        for (int j = 0; j < 4; j++) {
            float v = row[tid + j * 256];
            acc[j][0] += v * w.x; acc[j][1] += v * w.y;
            acc[j][2] += v * w.z; acc[j][3] += v * w.w;
        }
    }
#pragma unroll
    for (int j = 0; j < 4; j++) {
        int e = tid + j * 256;
#pragma unroll
        for (int h = 0; h < 4; h++)
            g_sent[(size_t)n * FF + e * 4 + h] = acc[j][h];
    }
}

// ---------------- persistent sentence BiLSTM scan (barrier slots 4/5) ----------------
#define SENT_NB_PER_DIR 32
#define SENT_SMEM ((16 * 4 * 512 + 512) * 4)

__global__ void sent_scan_kernel(const float* __restrict__ whh_f,
                                 const float* __restrict__ whh_b)
{
    extern __shared__ float sm[];
    float* ws = sm;                 // 16 e * 4 gates * 512 k
    float* hs = sm + 16 * 4 * 512;  // 512
    int dir = blockIdx.x >> 5;
    int bslot = blockIdx.x & 31;
    int e_base = bslot * 16;
    const float* whh = dir ? whh_b : whh_f;
    int tid = threadIdx.x;

    for (int idx = tid * 4; idx < 32768; idx += 256 * 4) {
        int gate = idx >> 13;
        int rem = idx & 8191;
        int el = rem >> 9;
        int k = rem & 511;
        *(float4*)&ws[idx] =
            *(const float4*)&whh[(size_t)((gate << 9) + e_base + el) * 512 + k];
    }
    int warp = tid >> 5, lane = tid & 31;
    int group = lane >> 3, lane8 = lane & 7;
    float creg[2] = {0.f, 0.f};
    __syncthreads();

    for (int s = 0; s < 256; s++) {
        int rd = s & 1;
        for (int i = tid; i < 512; i += 256)
            hs[i] = __ldcg(&g_sh[(rd * 2 + dir) * 512 + i]);
        __syncthreads();
        int nt = dir ? (255 - s) : s;
        const float* xrow = g_sxg + (size_t)nt * 4096 + (dir << 11);
#pragma unroll
        for (int i = 0; i < 2; i++) {
            int el = (warp << 1) + i;
            int e = e_base + el;
            const float4* w4 = (const float4*)&ws[((group << 4) + el) << 9];
            const float4* h4 = (const float4*)hs;
            float acc = 0.f;
#pragma unroll
            for (int m = 0; m < 16; m++) {
                float4 a = w4[lane8 + (m << 3)];
                float4 b = h4[lane8 + (m << 3)];
                acc += a.x * b.x + a.y * b.y + a.z * b.z + a.w * b.w;
            }
            acc += __shfl_xor_sync(0xffffffffu, acc, 1);
            acc += __shfl_xor_sync(0xffffffffu, acc, 2);
            acc += __shfl_xor_sync(0xffffffffu, acc, 4);
            float g = acc + xrow[(group << 9) + e];
            float gi = __shfl_sync(0xffffffffu, g, 0);
            float gf = __shfl_sync(0xffffffffu, g, 8);
            float gg = __shfl_sync(0xffffffffu, g, 16);
            float go = __shfl_sync(0xffffffffu, g, 24);
            if (lane == 0) {
                float c = creg[i];
                c = sigf(gf) * c + sigf(gi) * tanhf(gg);
                float h = sigf(go) * tanhf(c);
                creg[i] = c;
                int wr = rd ^ 1;
                g_sh[(wr * 2 + dir) * 512 + e] = h;
                g_sout[(size_t)nt * 1024 + (dir << 9) + e] = h;
            }
        }
        __syncthreads();
        grid_bar_strong(4 + dir, (unsigned)SENT_NB_PER_DIR, (unsigned)(s + 1));
    }
}

__global__ void final_kernel(const float* __restrict__ lw,
                             const float* __restrict__ lb,
                             float* __restrict__ out)
{
    int n = blockIdx.x, lane = threadIdx.x;
    const float* s = g_sout + (size_t)n * 1024;
    for (int c = 0; c < NLAB; c++) {
        float a = 0.f;
        for (int e = lane; e < 1024; e += 32) a += s[e] * lw[c * 1024 + e];
#pragma unroll
        for (int o = 16; o > 0; o >>= 1) a += __shfl_xor_sync(0xffffffffu, a, o);
        if (lane == 0) out[n * NLAB + c] = a + lb[c];
    }
}

// ---------------- launch ----------------
extern "C" void kernel_launch(void* const* d_in, const int* in_sizes, int n_in,
                              void* d_out, int out_size)
{
    const int*   tokens     = (const int*)d_in[0];
    const int*   lengths    = (const int*)d_in[1];
    const float* embedding  = (const float*)d_in[2];
    const float* tok_Wih_f  = (const float*)d_in[3];
    const float* tok_Whh_f  = (const float*)d_in[4];
    const float* tok_bih_f  = (const float*)d_in[5];
    const float* tok_bhh_f  = (const float*)d_in[6];
    const float* tok_Wih_b  = (const float*)d_in[7];
    const float* tok_Whh_b  = (const float*)d_in[8];
    const float* tok_bih_b  = (const float*)d_in[9];
    const float* tok_bhh_b  = (const float*)d_in[10];
    const float* attn_W     = (const float*)d_in[11];
    const float* attn_b     = (const float*)d_in[12];
    const float* attn_ctx   = (const float*)d_in[13];
    const float* sent_Wih_f = (const float*)d_in[14];
    const float* sent_Whh_f = (const float*)d_in[15];
    const float* sent_bih_f = (const float*)d_in[16];
    const float* sent_bhh_f = (const float*)d_in[17];
    const float* sent_Wih_b = (const float*)d_in[18];
    const float* sent_Whh_b = (const float*)d_in[19];
    const float* sent_bih_b = (const float*)d_in[20];
    const float* sent_bhh_b = (const float*)d_in[21];
    const float* lin_W      = (const float*)d_in[22];
    const float* lin_b      = (const float*)d_in[23];
    float* out = (float*)d_out;

    float *p_emb, *p_xg, *p_sent, *p_sxg, *p_btok, *p_bsent;
    cudaGetSymbolAddress((void**)&p_emb, g_emb);
    cudaGetSymbolAddress((void**)&p_xg, g_xg);
    cudaGetSymbolAddress((void**)&p_sent, g_sent);
    cudaGetSymbolAddress((void**)&p_sxg, g_sxg);
    cudaGetSymbolAddress((void**)&p_btok, g_bias_tok);
    cudaGetSymbolAddress((void**)&p_bsent, g_bias_sent);

    cudaFuncSetAttribute(sent_scan_kernel,
                         cudaFuncAttributeMaxDynamicSharedMemorySize, SENT_SMEM);
    cudaFuncSetAttribute(tok_scan_kernel,
                         cudaFuncAttributeMaxDynamicSharedMemorySize, TOK_SMEM);

    // launch 1: init state + bias precompute + attention fold (merged)
    initbias_kernel<<<2048, 256>>>(tok_bih_f, tok_bhh_f, tok_bih_b, tok_bhh_b,
                                   sent_bih_f, sent_bhh_f, sent_bih_b, sent_bhh_b,
                                   attn_W, attn_b, attn_ctx);
    // launch 2: embedding gather
    embed_kernel<<<(int)(((size_t)NLTOT * DI + 255) / 256), 256>>>(tokens, embedding);
    // launch 3: xg = emb @ [Wih_f;Wih_b]^T + biases (128x128 tiles, 2-stage)
    gemm2_kernel<<<dim3(16, 256, 2), 256>>>(p_emb, DI, tok_Wih_f, tok_Wih_b, DI,
                                            p_btok, p_xg, 4096, DI);
    // launch 4: persistent token BiLSTM scan, 256 threads (profiler slot)
    tok_scan_kernel<<<128, 256, TOK_SMEM>>>(tok_Whh_f, tok_Whh_b);

    // attention scores/softmax (full-grid streaming) + sentence feature
    scores_kernel<<<4096, 256>>>(lengths);
    sent_accum_kernel<<<256, 256>>>();

    // sentence input projection (M=256, N=2048/dir, K=4096)
    gemm2_kernel<<<dim3(16, 2, 2), 256>>>(p_sent, FF, sent_Wih_f, sent_Wih_b, FF,
                                          p_bsent, p_sxg, 4096, FF);

    // persistent sentence BiLSTM
    sent_scan_kernel<<<64, 256, SENT_SMEM>>>(sent_Whh_f, sent_Whh_b);

    final_kernel<<<256, 32>>>(lin_W, lin_b, out);
}

// round 16
// speedup vs baseline: 1.0836x; 1.0027x over previous
#include <cuda_runtime.h>
#include <cuda_bf16.h>
#include <math.h>

// Problem dims
#define NB   256      // batch (sentences)
#define LT   128      // tokens per sentence
#define DI   300      // embedding dim
#define EE   512      // LSTM hidden
#define G4   2048     // 4*E
#define FF   4096     // 2*E*HOP
#define HOPS 4
#define NLAB 7
#define NLTOT (NB*LT) // 32768

// ---------------- device scratch ----------------
__device__ float g_xg [(size_t)NLTOT * 4096];      // 537 MB : [n*128+l][dir*2048 + gate*512 + e]
__device__ float g_enc[(size_t)NLTOT * 1024];      // 134 MB : [n*128+l][dir*512 + e]
__device__ float g_h2[2 * 2 * NB * EE];            // [parity][dir][n][e]
__device__ float g_Mh[HOPS * 1024];
__device__ float g_s0[HOPS];
__device__ float g_attw[(size_t)NLTOT * HOPS];
__device__ float g_sent[(size_t)NB * FF];          // [n][e*4+h]
__device__ float g_sxg [(size_t)NB * 4096];        // [n][dir*2048 + gate*512 + e]
__device__ float g_sh[2 * 2 * EE];                 // [parity][dir][e]
__device__ float g_sout[(size_t)NB * 1024];        // [n][dir*512+e]
__device__ float g_bias_tok[4096];
__device__ float g_bias_sent[4096];
__device__ unsigned g_bar_cnt[8];
__device__ unsigned g_bar_flag[8];

__device__ __forceinline__ float sigf(float x) { return 1.f / (1.f + __expf(-x)); }

__device__ __forceinline__ unsigned f2tf32(float x)
{
    unsigned u;
    asm("cvt.rna.tf32.f32 %0, %1;" : "=r"(u) : "f"(x));
    return u;
}

__device__ __forceinline__ float4 cvt4(float4 v)
{
    v.x = __uint_as_float(f2tf32(v.x));
    v.y = __uint_as_float(f2tf32(v.y));
    v.z = __uint_as_float(f2tf32(v.z));
    v.w = __uint_as_float(f2tf32(v.w));
    return v;
}

__device__ __forceinline__ void mma8(float* c, const unsigned* a, const unsigned* b)
{
    asm volatile(
        "mma.sync.aligned.m16n8k8.row.col.f32.tf32.tf32.f32 "
        "{%0,%1,%2,%3},{%4,%5,%6,%7},{%8,%9},{%0,%1,%2,%3};"
        : "+f"(c[0]), "+f"(c[1]), "+f"(c[2]), "+f"(c[3])
        : "r"(a[0]), "r"(a[1]), "r"(a[2]), "r"(a[3]), "r"(b[0]), "r"(b[1]));
}

// grid barrier — round-6 proven form: arrival AND poll are strong atomics.
__device__ __forceinline__ void grid_bar_strong(int slot, unsigned arrivals, unsigned step)
{
    if (threadIdx.x == 0) {
        __threadfence();
        unsigned v = atomicAdd(&g_bar_cnt[slot], 1u);
        if (v == arrivals - 1u) {
            g_bar_cnt[slot] = 0u;
            __threadfence();
            atomicExch(&g_bar_flag[slot], step);
        } else {
            while (atomicAdd(&g_bar_flag[slot], 0u) < step) { }
            __threadfence();
        }
    }
    __syncthreads();
}

#define CP_ASYNC16(dst32, src) \
    asm volatile("cp.async.ca.shared.global [%0], [%1], 16;" :: "r"(dst32), "l"(src))
#define CP_COMMIT() asm volatile("cp.async.commit_group;")
#define CP_WAIT0()  asm volatile("cp.async.wait_group 0;")

// ---------------- tf32 SGEMM 128x128, 2-stage smem ping-pong ----------------
#define BM 128
#define BN 128
#define BK 16
#define AST 20   // (20*qr+qc) mod 32 all-distinct => conflict-free frag loads
#define BST 20

__device__ __forceinline__ float4 ldA(const float* ap, int kbase, int K)
{
    float4 v;
    if (kbase + 4 <= K) v = *(const float4*)ap;
    else {
        v.x = (kbase + 0 < K) ? ap[0] : 0.f;
        v.y = (kbase + 1 < K) ? ap[1] : 0.f;
        v.z = (kbase + 2 < K) ? ap[2] : 0.f;
        v.w = (kbase + 3 < K) ? ap[3] : 0.f;
    }
    return v;
}

// core: A rows given by two per-thread row pointers (a0row, a1row), K-major.
__device__ __forceinline__ void gemm_tf32_core(
    const float* __restrict__ a0row, const float* __restrict__ a1row,
    const float* __restrict__ B, int ldb,
    const float* __restrict__ bias,
    float* __restrict__ C, int ldc,
    int K, int m0, int n0,
    float* As, float* Bs)   // each holds 2 stages
{
    int tid = threadIdx.x;                 // 256 threads
    int warp = tid >> 5, lane = tid & 31;
    int wm = warp >> 2;                    // 0..1 -> m offset wm*64
    int wn = warp & 3;                     // 0..3 -> n offset wn*32
    int qr = lane >> 2;
    int qc = lane & 3;

    int lr = tid >> 2;                     // 0..63 (loader row)
    int lc = (tid & 3) << 2;               // 0,4,8,12 (loader k)

    float acc[4][4][4];
#pragma unroll
    for (int mf = 0; mf < 4; mf++)
#pragma unroll
        for (int nf = 0; nf < 4; nf++)
#pragma unroll
            for (int r = 0; r < 4; r++) acc[mf][nf][r] = 0.f;

    // preload k0 = 0
    float4 ra0 = ldA(a0row + lc, lc, K);
    float4 ra1 = ldA(a1row + lc, lc, K);
    float4 rb0 = ldA(B + (size_t)(n0 + lr) * ldb + lc, lc, K);
    float4 rb1 = ldA(B + (size_t)(n0 + lr + 64) * ldb + lc, lc, K);

    int it = 0;
    for (int k0 = 0; k0 < K; k0 += BK, it ^= 1) {
        float* Asp = As + it * (BM * AST);
        float* Bsp = Bs + it * (BN * BST);
        *(float4*)&Asp[lr * AST + lc] = cvt4(ra0);
        *(float4*)&Asp[(lr + 64) * AST + lc] = cvt4(ra1);
        *(float4*)&Bsp[lr * BST + lc] = cvt4(rb0);
        *(float4*)&Bsp[(lr + 64) * BST + lc] = cvt4(rb1);
        __syncthreads();

        int kn = k0 + BK;
        if (kn < K) {
            ra0 = ldA(a0row + kn + lc, kn + lc, K);
            ra1 = ldA(a1row + kn + lc, kn + lc, K);
            rb0 = ldA(B + (size_t)(n0 + lr) * ldb + kn + lc, kn + lc, K);
            rb1 = ldA(B + (size_t)(n0 + lr + 64) * ldb + kn + lc, kn + lc, K);
        }

#pragma unroll
        for (int kk = 0; kk < BK; kk += 8) {
            unsigned af[4][4], bf[4][2];
#pragma unroll
            for (int mf = 0; mf < 4; mf++) {
                int mb = (wm << 6) + (mf << 4) + qr;
                af[mf][0] = __float_as_uint(Asp[mb * AST + kk + qc]);
                af[mf][1] = __float_as_uint(Asp[(mb + 8) * AST + kk + qc]);
                af[mf][2] = __float_as_uint(Asp[mb * AST + kk + qc + 4]);
                af[mf][3] = __float_as_uint(Asp[(mb + 8) * AST + kk + qc + 4]);
            }
#pragma unroll
            for (int nf = 0; nf < 4; nf++) {
                int nb = (wn << 5) + (nf << 3) + qr;
                bf[nf][0] = __float_as_uint(Bsp[nb * BST + kk + qc]);
                bf[nf][1] = __float_as_uint(Bsp[nb * BST + kk + qc + 4]);
            }
#pragma unroll
            for (int mf = 0; mf < 4; mf++)
#pragma unroll
                for (int nf = 0; nf < 4; nf++)
                    mma8(acc[mf][nf], af[mf], bf[nf]);
        }
    }

#pragma unroll
    for (int mf = 0; mf < 4; mf++) {
#pragma unroll
        for (int nf = 0; nf < 4; nf++) {
            int n = n0 + (wn << 5) + (nf << 3) + (qc << 1);
#pragma unroll
            for (int rh = 0; rh < 2; rh++) {
                int m = m0 + (wm << 6) + (mf << 4) + qr + (rh << 3);
                float2 v;
                v.x = acc[mf][nf][rh * 2 + 0];
                v.y = acc[mf][nf][rh * 2 + 1];
                if (bias) { v.x += bias[n]; v.y += bias[n + 1]; }
                *(float2*)&C[(size_t)m * ldc + n] = v;
            }
        }
    }
}

// xg GEMM with fused embedding gather: A row m = embedding[tokens[m]]
__global__ void gemm_emb_kernel(const int* __restrict__ tokens,
                                const float* __restrict__ emb,
                                const float* __restrict__ B0, const float* __restrict__ B1,
                                int ldb, const float* __restrict__ bias4096,
                                float* __restrict__ C, int ldc, int K)
{
    __shared__ float As[2 * BM * AST];
    __shared__ float Bs[2 * BN * BST];
    int dir = blockIdx.z;
    const float* B = dir ? B1 : B0;
    const float* bias = bias4096 + dir * 2048;
    int m0 = blockIdx.y * BM;
    int lr = threadIdx.x >> 2;
    const float* a0row = emb + (size_t)tokens[m0 + lr] * DI;
    const float* a1row = emb + (size_t)tokens[m0 + lr + 64] * DI;
    gemm_tf32_core(a0row, a1row, B, ldb, bias,
                   C + dir * 2048, ldc, K, m0, blockIdx.x * BN, As, Bs);
}

// plain GEMM (sentence projection): A dense
__global__ void gemm2_kernel(const float* __restrict__ A, int lda,
                             const float* __restrict__ B0, const float* __restrict__ B1,
                             int ldb, const float* __restrict__ bias4096,
                             float* __restrict__ C, int ldc, int K)
{
    __shared__ float As[2 * BM * AST];
    __shared__ float Bs[2 * BN * BST];
    int dir = blockIdx.z;
    const float* B = dir ? B1 : B0;
    const float* bias = bias4096 ? (bias4096 + dir * 2048) : nullptr;
    int m0 = blockIdx.y * BM;
    int lr = threadIdx.x >> 2;
    const float* a0row = A + (size_t)(m0 + lr) * lda;
    const float* a1row = A + (size_t)(m0 + lr + 64) * lda;
    gemm_tf32_core(a0row, a1row, B, ldb, bias,
                   C + dir * 2048, ldc, K, m0, blockIdx.x * BN, As, Bs);
}

// ---------------- persistent token BiLSTM scan (256 threads, proven shape) ----
// Ws pair-permuted k-layout (k=qc, k=qc+4 adjacent), stride 520 -> LDS.64 B-frags.
#define TOK_WST 520
#define TOK_HST 36
#define TOK_OST 68
#define XST     68
#define TOK_HB0 (64 * TOK_WST)
#define TOK_XS  (64 * TOK_WST + 2 * 128 * TOK_HST)
#define TOK_SMEM ((64 * TOK_WST + 2 * 128 * TOK_HST + 128 * XST) * 4)

__global__ void __launch_bounds__(256, 1) tok_scan_kernel(
    const float* __restrict__ whh_f, const float* __restrict__ whh_b)
{
    extern __shared__ float sm[];
    float* Ws = sm;                 // 64 x 520 tf32 weights, pair-permuted k
    float* Os = sm + TOK_HB0;       // 128 x 68 gemm output (aliases the two Hb buffers)
    float* Xs = sm + TOK_XS;        // 128 x 68 xg gate tile

    int tid = threadIdx.x;
    int warp = tid >> 5, lane = tid & 31;
    int wm = warp & 3, wn = warp >> 2;
    int qr = lane >> 2, qc = lane & 3;

    int dir = blockIdx.x >> 6;
    int rem = blockIdx.x & 63;
    int bh = rem >> 5;
    int es = rem & 31;
    int e_base = es << 4;
    int nb0 = bh << 7;
    int bslot = dir * 2 + bh;

    const float* whh = dir ? whh_b : whh_f;

    for (int idx = tid * 4; idx < 64 * 512; idx += 1024) {
        int r = idx >> 9, k = idx & 511;
        int gate = r >> 4, el = r & 15;
        float4 w = cvt4(*(const float4*)&whh[(size_t)((gate << 9) + e_base + el) * 512 + k]);
        int base = r * TOK_WST + (k & ~7);
        int off = (k & 4) ? 1 : 0;
        Ws[base + off + 0] = w.x;
        Ws[base + off + 2] = w.y;
        Ws[base + off + 4] = w.z;
        Ws[base + off + 6] = w.w;
    }

    int gp_e = tid & 15;
    int gp_n = tid >> 4;
    float creg[8];
#pragma unroll
    for (int j = 0; j < 8; j++) creg[j] = 0.f;

    int clr = tid >> 3;
    int clc = (tid & 7) << 2;

    unsigned xs_addr = (unsigned)__cvta_generic_to_shared(Xs);

    __syncthreads();

    for (int s = 0; s < LT; s++) {
        int p = s & 1;
        int l = dir ? (LT - 1 - s) : s;

        {
            const float* xbase = g_xg + (size_t)(nb0 * LT + l) * 4096 + (dir << 11) + e_base;
#pragma unroll
            for (int j = 0; j < 8; j++) {
                int i = tid + (j << 8);
                int row = i >> 4;
                int q = i & 15;
                int gate = q >> 2, v4 = (q & 3) << 2;
                const float* src = xbase + (size_t)row * (LT * 4096) + (gate << 9) + v4;
                CP_ASYNC16(xs_addr + (unsigned)((row * XST + (gate << 4) + v4) << 2), src);
            }
            CP_COMMIT();
        }

        const float* hsrc = g_h2 + (size_t)((p * 2 + dir) * NB + nb0) * EE;

        float acc[2][4][4];
#pragma unroll
        for (int mf = 0; mf < 2; mf++)
#pragma unroll
            for (int nf = 0; nf < 4; nf++)
#pragma unroll
                for (int r = 0; r < 4; r++) acc[mf][nf][r] = 0.f;

        float4 pre[4];
#pragma unroll
        for (int pp = 0; pp < 4; pp++)
            pre[pp] = *(const float4*)(hsrc + (size_t)(clr + (pp << 5)) * EE + clc);

        for (int ck = 0; ck < 16; ck++) {
            float* Hc = sm + TOK_HB0 + (ck & 1) * (128 * TOK_HST);
            int k0 = ck << 5;
#pragma unroll
            for (int pp = 0; pp < 4; pp++)
                *(float4*)&Hc[(clr + (pp << 5)) * TOK_HST + clc] = cvt4(pre[pp]);
            __syncthreads();

            if (ck < 15) {
#pragma unroll
                for (int pp = 0; pp < 4; pp++)
                    pre[pp] = *(const float4*)(hsrc + (size_t)(clr + (pp << 5)) * EE + k0 + 32 + clc);
            }

#pragma unroll
            for (int kk = 0; kk < 32; kk += 8) {
                unsigned af[2][4], bf[4][2];
#pragma unroll
                for (int mf = 0; mf < 2; mf++) {
                    int mb = (wm << 5) + (mf << 4) + qr;
                    af[mf][0] = __float_as_uint(Hc[mb * TOK_HST + kk + qc]);
                    af[mf][1] = __float_as_uint(Hc[(mb + 8) * TOK_HST + kk + qc]);
                    af[mf][2] = __float_as_uint(Hc[mb * TOK_HST + kk + qc + 4]);
                    af[mf][3] = __float_as_uint(Hc[(mb + 8) * TOK_HST + kk + qc + 4]);
                }
#pragma unroll
                for (int nf = 0; nf < 4; nf++) {
                    int nb = (wn << 5) + (nf << 3) + qr;
                    float2 b2 = *(const float2*)&Ws[nb * TOK_WST + k0 + kk + (qc << 1)];
                    bf[nf][0] = __float_as_uint(b2.x);
                    bf[nf][1] = __float_as_uint(b2.y);
                }
#pragma unroll
                for (int mf = 0; mf < 2; mf++)
#pragma unroll
                    for (int nf = 0; nf < 4; nf++)
                        mma8(acc[mf][nf], af[mf], bf[nf]);
            }
        }
        __syncthreads();

#pragma unroll
        for (int mf = 0; mf < 2; mf++)
#pragma unroll
            for (int nf = 0; nf < 4; nf++) {
                int cc = (wn << 5) + (nf << 3) + (qc << 1);
#pragma unroll
                for (int rh = 0; rh < 2; rh++) {
                    int rr = (wm << 5) + (mf << 4) + qr + (rh << 3);
                    Os[rr * TOK_OST + cc] = acc[mf][nf][rh * 2 + 0];
                    Os[rr * TOK_OST + cc + 1] = acc[mf][nf][rh * 2 + 1];
                }
            }
        CP_WAIT0();
        __syncthreads();

        float* hdst = g_h2 + (size_t)(((p ^ 1) * 2 + dir) * NB + nb0) * EE;
#pragma unroll
        for (int j = 0; j < 8; j++) {
            int nn = gp_n + (j << 4);
            int ng = nb0 + nn;
            float gi = Os[nn * TOK_OST + gp_e]      + Xs[nn * XST + gp_e];
            float gf = Os[nn * TOK_OST + 16 + gp_e] + Xs[nn * XST + 16 + gp_e];
            float gg = Os[nn * TOK_OST + 32 + gp_e] + Xs[nn * XST + 32 + gp_e];
            float go = Os[nn * TOK_OST + 48 + gp_e] + Xs[nn * XST + 48 + gp_e];
            float c = creg[j];
            c = sigf(gf) * c + sigf(gi) * tanhf(gg);
            float h = sigf(go) * tanhf(c);
            creg[j] = c;
            hdst[(size_t)nn * EE + e_base + gp_e] = h;
            g_enc[((size_t)ng * LT + l) * 1024 + (dir << 9) + e_base + gp_e] = h;
        }
        __syncthreads();

        grid_bar_strong(bslot, 32u, (unsigned)(s + 1));
    }
}

// ---------------- misc kernels ----------------
__global__ void initbias_kernel(const float* b0, const float* b1, const float* b2, const float* b3,
                                const float* s0, const float* s1, const float* s2, const float* s3,
                                const float* __restrict__ W, const float* __restrict__ b,
                                const float* __restrict__ ctx)
{
    int i = blockIdx.x * 256 + threadIdx.x;
    if (i < 2 * 2 * NB * EE) g_h2[i] = 0.f;
    if (i < 2 * 2 * EE) g_sh[i] = 0.f;
    if (i < 8) { g_bar_cnt[i] = 0u; g_bar_flag[i] = 0u; }
    if (i < 2048) {
        g_bias_tok[i] = b0[i] + b1[i];
        g_bias_sent[i] = s0[i] + s1[i];
    } else if (i < 4096) {
        int j = i - 2048;
        g_bias_tok[i] = b2[j] + b3[j];
        g_bias_sent[i] = s2[j] + s3[j];
    }
    if (i < HOPS * 1024) {
        int h = i >> 10, e = i & 1023;
        float s = 0.f;
        for (int a = 0; a < 256; a++) s += ctx[h * 256 + a] * W[a * 1024 + e];
        g_Mh[i] = s;
    }
    if (i < HOPS) {
        float s = 0.f;
        for (int a = 0; a < 256; a++) s += ctx[i * 256 + a] * b[a];
        g_s0[i] = s;
    }
}

__global__ void scores_kernel(const int* __restrict__ lengths)
{
    __shared__ float Msh[4096];
    __shared__ float s0s[4];
    int tid = threadIdx.x;
    for (int i = tid; i < 4096; i += 256) Msh[i] = g_Mh[i];
    if (tid < 4) s0s[tid] = g_s0[tid];
    __syncthreads();
    int gid = blockIdx.x * 8 + (tid >> 5);
    int lane = tid & 31;
    int n = gid >> 7, l = gid & 127;
    const float* row = g_enc + (size_t)gid * 1024;
    float a0 = 0, a1 = 0, a2 = 0, a3 = 0;
    for (int e = lane; e < 1024; e += 32) {
        float v = row[e];
        a0 += v * Msh[e];        a1 += v * Msh[1024 + e];
        a2 += v * Msh[2048 + e]; a3 += v * Msh[3072 + e];
    }
#pragma unroll
    for (int o = 16; o > 0; o >>= 1) {
        a0 += __shfl_xor_sync(0xffffffffu, a0, o);
        a1 += __shfl_xor_sync(0xffffffffu, a1, o);
        a2 += __shfl_xor_sync(0xffffffffu, a2, o);
        a3 += __shfl_xor_sync(0xffffffffu, a3, o);
    }
    if (lane == 0) {
        a0 += s0s[0]; a1 += s0s[1]; a2 += s0s[2]; a3 += s0s[3];
        float mx = fmaxf(fmaxf(a0, a1), fmaxf(a2, a3));
        float e0 = __expf(a0 - mx), e1 = __expf(a1 - mx);
        float e2 = __expf(a2 - mx), e3 = __expf(a3 - mx);
        float inv = 1.f / (e0 + e1 + e2 + e3);
        float msk = (l < lengths[n]) ? 1.f : 0.f;
        float4 w = make_float4(e0 * inv * msk, e1 * inv * msk, e2 * inv * msk, e3 * inv * msk);
        *(float4*)&g_attw[(size_t)gid * 4] = w;
    }
}

__global__ void sent_accum_kernel()
{
    int n = blockIdx.x, tid = threadIdx.x;
    float acc[4][4];
#pragma unroll
    for (int j = 0; j < 4; j++)
#pragma unroll
        for (int h = 0; h < 4; h++) acc[j][h] = 0.f;
    const float* encn = g_enc + (size_t)n * LT * 1024;
    const float* wv = g_attw + (size_t)n * LT * 4;
    for (int l = 0; l < LT; l++) {
        float4 w = *(const float4*)&wv[l * 4];
        const float* row = encn + (size_t)l * 1024;
#pragma unroll
        for (int j = 0; j < 4; j++) {
            float v = row[tid + j * 256];
            acc[j][0] += v * w.x; acc[j][1] += v * w.y;
            acc[j][2] += v * w.z; acc[j][3] += v * w.w;
        }
    }
#pragma unroll
    for (int j = 0; j < 4; j++) {
        int e = tid + j * 256;
#pragma unroll
        for (int h = 0; h < 4; h++)
            g_sent[(size_t)n * FF + e * 4 + h] = acc[j][h];
    }
}

// ---------------- persistent sentence BiLSTM scan (barrier slots 4/5) ----------------
#define SENT_NB_PER_DIR 32
#define SENT_SMEM ((16 * 4 * 512 + 512) * 4)

__global__ void sent_scan_kernel(const float* __restrict__ whh_f,
                                 const float* __restrict__ whh_b)
{
    extern __shared__ float sm[];
    float* ws = sm;                 // 16 e * 4 gates * 512 k
    float* hs = sm + 16 * 4 * 512;  // 512
    int dir = blockIdx.x >> 5;
    int bslot = blockIdx.x & 31;
    int e_base = bslot * 16;
    const float* whh = dir ? whh_b : whh_f;
    int tid = threadIdx.x;

    for (int idx = tid * 4; idx < 32768; idx += 256 * 4) {
        int gate = idx >> 13;
        int rem = idx & 8191;
        int el = rem >> 9;
        int k = rem & 511;
        *(float4*)&ws[idx] =
            *(const float4*)&whh[(size_t)((gate << 9) + e_base + el) * 512 + k];
    }
    int warp = tid >> 5, lane = tid & 31;
    int group = lane >> 3, lane8 = lane & 7;
    float creg[2] = {0.f, 0.f};
    __syncthreads();

    for (int s = 0; s < 256; s++) {
        int rd = s & 1;
        for (int i = tid; i < 512; i += 256)
            hs[i] = __ldcg(&g_sh[(rd * 2 + dir) * 512 + i]);
        __syncthreads();
        int nt = dir ? (255 - s) : s;
        const float* xrow = g_sxg + (size_t)nt * 4096 + (dir << 11);
#pragma unroll
        for (int i = 0; i < 2; i++) {
            int el = (warp << 1) + i;
            int e = e_base + el;
            const float4* w4 = (const float4*)&ws[((group << 4) + el) << 9];
            const float4* h4 = (const float4*)hs;
            float acc = 0.f;
#pragma unroll
            for (int m = 0; m < 16; m++) {
                float4 a = w4[lane8 + (m << 3)];
                float4 b = h4[lane8 + (m << 3)];
                acc += a.x * b.x + a.y * b.y + a.z * b.z + a.w * b.w;
            }
            acc += __shfl_xor_sync(0xffffffffu, acc, 1);
            acc += __shfl_xor_sync(0xffffffffu, acc, 2);
            acc += __shfl_xor_sync(0xffffffffu, acc, 4);
            float g = acc + xrow[(group << 9) + e];
            float gi = __shfl_sync(0xffffffffu, g, 0);
            float gf = __shfl_sync(0xffffffffu, g, 8);
            float gg = __shfl_sync(0xffffffffu, g, 16);
            float go = __shfl_sync(0xffffffffu, g, 24);
            if (lane == 0) {
                float c = creg[i];
                c = sigf(gf) * c + sigf(gi) * tanhf(gg);
                float h = sigf(go) * tanhf(c);
                creg[i] = c;
                int wr = rd ^ 1;
                g_sh[(wr * 2 + dir) * 512 + e] = h;
                g_sout[(size_t)nt * 1024 + (dir << 9) + e] = h;
            }
        }
        __syncthreads();
        grid_bar_strong(4 + dir, (unsigned)SENT_NB_PER_DIR, (unsigned)(s + 1));
    }
}

__global__ void final_kernel(const float* __restrict__ lw,
                             const float* __restrict__ lb,
                             float* __restrict__ out)
{
    int n = blockIdx.x, lane = threadIdx.x;
    const float* s = g_sout + (size_t)n * 1024;
    for (int c = 0; c < NLAB; c++) {
        float a = 0.f;
        for (int e = lane; e < 1024; e += 32) a += s[e] * lw[c * 1024 + e];
#pragma unroll
        for (int o = 16; o > 0; o >>= 1) a += __shfl_xor_sync(0xffffffffu, a, o);
        if (lane == 0) out[n * NLAB + c] = a + lb[c];
    }
}

// ---------------- launch ----------------
extern "C" void kernel_launch(void* const* d_in, const int* in_sizes, int n_in,
                              void* d_out, int out_size)
{
    const int*   tokens     = (const int*)d_in[0];
    const int*   lengths    = (const int*)d_in[1];
    const float* embedding  = (const float*)d_in[2];
    const float* tok_Wih_f  = (const float*)d_in[3];
    const float* tok_Whh_f  = (const float*)d_in[4];
    const float* tok_bih_f  = (const float*)d_in[5];
    const float* tok_bhh_f  = (const float*)d_in[6];
    const float* tok_Wih_b  = (const float*)d_in[7];
    const float* tok_Whh_b  = (const float*)d_in[8];
    const float* tok_bih_b  = (const float*)d_in[9];
    const float* tok_bhh_b  = (const float*)d_in[10];
    const float* attn_W     = (const float*)d_in[11];
    const float* attn_b     = (const float*)d_in[12];
    const float* attn_ctx   = (const float*)d_in[13];
    const float* sent_Wih_f = (const float*)d_in[14];
    const float* sent_Whh_f = (const float*)d_in[15];
    const float* sent_bih_f = (const float*)d_in[16];
    const float* sent_bhh_f = (const float*)d_in[17];
    const float* sent_Wih_b = (const float*)d_in[18];
    const float* sent_Whh_b = (const float*)d_in[19];
    const float* sent_bih_b = (const float*)d_in[20];
    const float* sent_bhh_b = (const float*)d_in[21];
    const float* lin_W      = (const float*)d_in[22];
    const float* lin_b      = (const float*)d_in[23];
    float* out = (float*)d_out;

    float *p_xg, *p_sent, *p_sxg, *p_btok, *p_bsent;
    cudaGetSymbolAddress((void**)&p_xg, g_xg);
    cudaGetSymbolAddress((void**)&p_sent, g_sent);
    cudaGetSymbolAddress((void**)&p_sxg, g_sxg);
    cudaGetSymbolAddress((void**)&p_btok, g_bias_tok);
    cudaGetSymbolAddress((void**)&p_bsent, g_bias_sent);

    cudaFuncSetAttribute(sent_scan_kernel,
                         cudaFuncAttributeMaxDynamicSharedMemorySize, SENT_SMEM);
    cudaFuncSetAttribute(tok_scan_kernel,
                         cudaFuncAttributeMaxDynamicSharedMemorySize, TOK_SMEM);

    // launch 1: init state + bias precompute + attention fold (merged)
    initbias_kernel<<<2048, 256>>>(tok_bih_f, tok_bhh_f, tok_bih_b, tok_bhh_b,
                                   sent_bih_f, sent_bhh_f, sent_bih_b, sent_bhh_b,
                                   attn_W, attn_b, attn_ctx);
    // launch 2: xg = emb[tokens] @ [Wih_f;Wih_b]^T + biases (fused gather GEMM)
    gemm_emb_kernel<<<dim3(16, 256, 2), 256>>>(tokens, embedding, tok_Wih_f, tok_Wih_b,
                                               DI, p_btok, p_xg, 4096, DI);
    // launch 3: persistent token BiLSTM scan
    tok_scan_kernel<<<128, 256, TOK_SMEM>>>(tok_Whh_f, tok_Whh_b);

    // attention scores/softmax (full-grid streaming) + sentence feature
    scores_kernel<<<4096, 256>>>(lengths);
    sent_accum_kernel<<<256, 256>>>();

    // sentence input projection (M=256, N=2048/dir, K=4096)
    gemm2_kernel<<<dim3(16, 2, 2), 256>>>(p_sent, FF, sent_Wih_f, sent_Wih_b, FF,
                                          p_bsent, p_sxg, 4096, FF);

    // persistent sentence BiLSTM
    sent_scan_kernel<<<64, 256, SENT_SMEM>>>(sent_Whh_f, sent_Whh_b);

    final_kernel<<<256, 32>>>(lin_W, lin_b, out);
}